// round 14
// baseline (speedup 1.0000x reference)
#include <cuda_runtime.h>
#include <cuda_fp16.h>
#include <cstdint>

#define H_HEADS   32
#define KV_HEADS  8
#define HEAD_DIM  128
#define HIDDEN    2048
#define QLEN      1024
#define CTXLEN    2048
#define TLEN      3072
#define QKDIM     (H_HEADS * HEAD_DIM)    // 4096
#define KVDIM     (KV_HEADS * HEAD_DIM)   // 1024

// ---------------- scratch ----------------
__device__ __half g_Xh  [TLEN * HIDDEN];
__device__ __half g_Wqh [QKDIM * HIDDEN];
__device__ __half g_Wkvh[2 * KVDIM * HIDDEN];
__device__ __half g_Woh [HIDDEN * QKDIM];
__device__ float  g_Qraw[QLEN * QKDIM];
__device__ float  g_Kraw[TLEN * KVDIM];
__device__ __half g_Qh  [QLEN * QKDIM];
__device__ __half g_Kh  [TLEN * KVDIM];
__device__ __half g_Vh  [TLEN * KVDIM];
__device__ __half g_Oh  [QLEN * QKDIM];

// ---------------- helpers ----------------
__device__ __forceinline__ uint32_t smem_u32(const void* p) {
    return (uint32_t)__cvta_generic_to_shared(p);
}
__device__ __forceinline__ void ldsm4(uint32_t& r0, uint32_t& r1, uint32_t& r2, uint32_t& r3, uint32_t a) {
    asm volatile("ldmatrix.sync.aligned.m8n8.x4.shared.b16 {%0,%1,%2,%3},[%4];\n"
                 : "=r"(r0), "=r"(r1), "=r"(r2), "=r"(r3) : "r"(a));
}
__device__ __forceinline__ void ldsm4t(uint32_t& r0, uint32_t& r1, uint32_t& r2, uint32_t& r3, uint32_t a) {
    asm volatile("ldmatrix.sync.aligned.m8n8.x4.trans.shared.b16 {%0,%1,%2,%3},[%4];\n"
                 : "=r"(r0), "=r"(r1), "=r"(r2), "=r"(r3) : "r"(a));
}
__device__ __forceinline__ void mma16816(float* c, uint32_t a0, uint32_t a1, uint32_t a2, uint32_t a3,
                                         uint32_t b0, uint32_t b1) {
    asm volatile("mma.sync.aligned.m16n8k16.row.col.f32.f16.f16.f32 "
                 "{%0,%1,%2,%3},{%4,%5,%6,%7},{%8,%9},{%0,%1,%2,%3};\n"
                 : "+f"(c[0]), "+f"(c[1]), "+f"(c[2]), "+f"(c[3])
                 : "r"(a0), "r"(a1), "r"(a2), "r"(a3), "r"(b0), "r"(b1));
}
__device__ __forceinline__ uint32_t packh2(float a, float b) {
    __half2 h = __floats2half2_rn(a, b);
    return *reinterpret_cast<uint32_t*>(&h);
}
__device__ __forceinline__ uint32_t h2exp2(uint32_t x) {
    uint32_t r;
    asm("ex2.approx.f16x2 %0, %1;" : "=r"(r) : "r"(x));
    return r;
}
__device__ __forceinline__ void cpa16(uint32_t dst, const void* src) {
    asm volatile("cp.async.cg.shared.global [%0],[%1],16;\n" :: "r"(dst), "l"(src));
}
__device__ __forceinline__ void cpa_commit() { asm volatile("cp.async.commit_group;\n"); }
template <int N> __device__ __forceinline__ void cpa_wait() {
    asm volatile("cp.async.wait_group %0;\n" :: "n"(N));
}
__device__ __forceinline__ void st2(float* p, float a, float b) { *(float2*)p = make_float2(a, b); }
__device__ __forceinline__ void st2(__half* p, float a, float b) { *(__half2*)p = __floats2half2_rn(a, b); }

// ---------------- fused fp32 -> fp16 conversion ----------------
__global__ void cvt6(const float* s0, __half* d0, int n0, const float* s1, __half* d1, int n1,
                     const float* s2, __half* d2, int n2, const float* s3, __half* d3, int n3,
                     const float* s4, __half* d4, int n4c, const float* s5, __half* d5, int n5) {
    int total = n0 + n1 + n2 + n3 + n4c + n5;
    int stride = gridDim.x * blockDim.x;
    for (int i = blockIdx.x * blockDim.x + threadIdx.x; i < total; i += stride) {
        const float* s; __half* d; int j = i;
        if (j < n0) { s = s0; d = d0; }
        else if ((j -= n0) < n1) { s = s1; d = d1; }
        else if ((j -= n1) < n2) { s = s2; d = d2; }
        else if ((j -= n2) < n3) { s = s3; d = d3; }
        else if ((j -= n3) < n4c) { s = s4; d = d4; }
        else { j -= n4c; s = s5; d = d5; }
        float4 a = reinterpret_cast<const float4*>(s)[2 * j];
        float4 b = reinterpret_cast<const float4*>(s)[2 * j + 1];
        __half2 h0 = __floats2half2_rn(a.x, a.y), h1 = __floats2half2_rn(a.z, a.w);
        __half2 h2 = __floats2half2_rn(b.x, b.y), h3 = __floats2half2_rn(b.z, b.w);
        uint4 o;
        o.x = *(uint32_t*)&h0; o.y = *(uint32_t*)&h1; o.z = *(uint32_t*)&h2; o.w = *(uint32_t*)&h3;
        reinterpret_cast<uint4*>(d)[j] = o;
    }
}

// =========================================================================
// Merged Q+KV projection: 4 stages, barrier every 2 k-iterations.
// =========================================================================
#define GSA 40
#define G_STAGES 4
#define G_ASTRIDE (128 * GSA)
#define G_SMEM128 (G_STAGES * G_ASTRIDE * 2 * 2)   // 81,920 B

__global__ __launch_bounds__(256, 2) void gemm_qkv(const __half* __restrict__ Xh,
                                                   const __half* __restrict__ Wqh,
                                                   const __half* __restrict__ Wkvh,
                                                   float* __restrict__ Qraw,
                                                   float* __restrict__ Kraw,
                                                   __half* __restrict__ Vh) {
    extern __shared__ __align__(16) __half gsm[];
    __half* As = gsm;
    __half* Bs = gsm + G_STAGES * G_ASTRIDE;
    const int tid = threadIdx.x, lane = tid & 31, w = tid >> 5;
    const int bid = blockIdx.x;
    const bool isQ = bid < 256;
    const __half* A;
    const __half* B;
    int bm, bn;
    if (isQ) {
        A = Xh + (size_t)CTXLEN * HIDDEN;
        B = Wqh;
        bm = (bid >> 5) << 7;
        bn = (bid & 31) << 7;
    } else {
        int b = bid - 256;
        A = Xh;
        B = Wkvh;
        bm = (b >> 4) << 7;
        bn = (b & 15) << 7;
    }
    const int wm = (w >> 1) << 5, wn = (w & 1) << 6;
    constexpr int K = HIDDEN;

    float acc[2][8][4];
#pragma unroll
    for (int i = 0; i < 2; i++)
#pragma unroll
        for (int j = 0; j < 8; j++)
#pragma unroll
            for (int k = 0; k < 4; k++) acc[i][j][k] = 0.f;

    const int r = tid >> 2, cch = (tid & 3) << 3;
    const int nt = K >> 5;   // 64 (even)

    auto load_stage = [&](int t, int s) {
        int k0 = t << 5;
        cpa16(smem_u32(&As[s * G_ASTRIDE + r * GSA + cch]),        &A[(size_t)(bm + r) * K + k0 + cch]);
        cpa16(smem_u32(&As[s * G_ASTRIDE + (r + 64) * GSA + cch]), &A[(size_t)(bm + r + 64) * K + k0 + cch]);
        cpa16(smem_u32(&Bs[s * G_ASTRIDE + r * GSA + cch]),        &B[(size_t)(bn + r) * K + k0 + cch]);
        cpa16(smem_u32(&Bs[s * G_ASTRIDE + (r + 64) * GSA + cch]), &B[(size_t)(bn + r + 64) * K + k0 + cch]);
    };
    auto compute = [&](int s) {
        const __half* as = As + s * G_ASTRIDE;
        const __half* bs = Bs + s * G_ASTRIDE;
#pragma unroll
        for (int kk = 0; kk < 2; kk++) {
            uint32_t a[2][4];
#pragma unroll
            for (int mt = 0; mt < 2; mt++) {
                uint32_t ad = smem_u32(&as[(wm + mt * 16 + (lane & 15)) * GSA + kk * 16 + ((lane >> 4) << 3)]);
                ldsm4(a[mt][0], a[mt][1], a[mt][2], a[mt][3], ad);
            }
#pragma unroll
            for (int n2 = 0; n2 < 4; n2++) {
                uint32_t b0, b1, b2, b3;
                uint32_t ad = smem_u32(&bs[(wn + n2 * 16 + ((lane >> 4) << 3) + (lane & 7)) * GSA +
                                           kk * 16 + (((lane >> 3) & 1) << 3)]);
                ldsm4(b0, b1, b2, b3, ad);
#pragma unroll
                for (int mt = 0; mt < 2; mt++) {
                    mma16816(acc[mt][2 * n2],     a[mt][0], a[mt][1], a[mt][2], a[mt][3], b0, b1);
                    mma16816(acc[mt][2 * n2 + 1], a[mt][0], a[mt][1], a[mt][2], a[mt][3], b2, b3);
                }
            }
        }
    };

    load_stage(0, 0); cpa_commit();
    load_stage(1, 1); cpa_commit();

    for (int t = 0; t < nt; t += 2) {
        cpa_wait<1>();
        __syncthreads();                 // one barrier per 2 k-iterations
        if (t + 2 < nt) load_stage(t + 2, (t + 2) & 3);
        cpa_commit();
        compute(t & 3);
        cpa_wait<1>();
        if (t + 3 < nt) load_stage(t + 3, (t + 3) & 3);
        cpa_commit();
        compute((t + 1) & 3);
    }

    const int g = lane >> 2, c = (lane & 3) << 1;
    if (isQ) {
#pragma unroll
        for (int mt = 0; mt < 2; mt++)
#pragma unroll
            for (int ntl = 0; ntl < 8; ntl++) {
                int row = bm + wm + mt * 16 + g;
                int col = bn + wn + ntl * 8 + c;
                st2(&Qraw[(size_t)row * QKDIM + col],       acc[mt][ntl][0], acc[mt][ntl][1]);
                st2(&Qraw[(size_t)(row + 8) * QKDIM + col], acc[mt][ntl][2], acc[mt][ntl][3]);
            }
    } else {
        const bool isK = bn < KVDIM;
        const int colbase = bn - (isK ? 0 : KVDIM) + wn;
#pragma unroll
        for (int mt = 0; mt < 2; mt++)
#pragma unroll
            for (int ntl = 0; ntl < 8; ntl++) {
                int row = bm + wm + mt * 16 + g;
                int col = colbase + ntl * 8 + c;
                if (isK) {
                    st2(&Kraw[(size_t)row * KVDIM + col],       acc[mt][ntl][0], acc[mt][ntl][1]);
                    st2(&Kraw[(size_t)(row + 8) * KVDIM + col], acc[mt][ntl][2], acc[mt][ntl][3]);
                } else {
                    st2(&Vh[(size_t)row * KVDIM + col],       acc[mt][ntl][0], acc[mt][ntl][1]);
                    st2(&Vh[(size_t)(row + 8) * KVDIM + col], acc[mt][ntl][2], acc[mt][ntl][3]);
                }
            }
    }
}

// ---------------- O-projection GEMM: 4 stages, barrier every 2 iters ----------------
#define GO_BSTRIDE (64 * GSA)
#define GO_SMEM (G_STAGES * (G_ASTRIDE + GO_BSTRIDE) * 2)   // 61,440 B
__global__ __launch_bounds__(256, 2) void gemm_o(const __half* __restrict__ A,
                                                 const __half* __restrict__ B,
                                                 float* __restrict__ C) {
    constexpr int NB = 64, K = QKDIM, N = HIDDEN;
    extern __shared__ __align__(16) __half gsm[];
    __half* As = gsm;
    __half* Bs = gsm + G_STAGES * G_ASTRIDE;
    const int tid = threadIdx.x, lane = tid & 31, w = tid >> 5;
    const int bm = blockIdx.y << 7, bn = blockIdx.x * NB;
    const int wm = (w >> 1) << 5, wn = (w & 1) << 5;

    float acc[2][4][4];
#pragma unroll
    for (int i = 0; i < 2; i++)
#pragma unroll
        for (int j = 0; j < 4; j++)
#pragma unroll
            for (int k = 0; k < 4; k++) acc[i][j][k] = 0.f;

    const int r = tid >> 2, cch = (tid & 3) << 3;
    const int nt = K >> 5;   // 128 (even)

    auto load_stage = [&](int t, int s) {
        int k0 = t << 5;
        cpa16(smem_u32(&As[s * G_ASTRIDE + r * GSA + cch]),        &A[(size_t)(bm + r) * K + k0 + cch]);
        cpa16(smem_u32(&As[s * G_ASTRIDE + (r + 64) * GSA + cch]), &A[(size_t)(bm + r + 64) * K + k0 + cch]);
        cpa16(smem_u32(&Bs[s * GO_BSTRIDE + r * GSA + cch]),       &B[(size_t)(bn + r) * K + k0 + cch]);
    };
    auto compute = [&](int s) {
        const __half* as = As + s * G_ASTRIDE;
        const __half* bs = Bs + s * GO_BSTRIDE;
#pragma unroll
        for (int kk = 0; kk < 2; kk++) {
            uint32_t a[2][4];
#pragma unroll
            for (int mt = 0; mt < 2; mt++) {
                uint32_t ad = smem_u32(&as[(wm + mt * 16 + (lane & 15)) * GSA + kk * 16 + ((lane >> 4) << 3)]);
                ldsm4(a[mt][0], a[mt][1], a[mt][2], a[mt][3], ad);
            }
#pragma unroll
            for (int n2 = 0; n2 < 2; n2++) {
                uint32_t b0, b1, b2, b3;
                uint32_t ad = smem_u32(&bs[(wn + n2 * 16 + ((lane >> 4) << 3) + (lane & 7)) * GSA +
                                           kk * 16 + (((lane >> 3) & 1) << 3)]);
                ldsm4(b0, b1, b2, b3, ad);
#pragma unroll
                for (int mt = 0; mt < 2; mt++) {
                    mma16816(acc[mt][2 * n2],     a[mt][0], a[mt][1], a[mt][2], a[mt][3], b0, b1);
                    mma16816(acc[mt][2 * n2 + 1], a[mt][0], a[mt][1], a[mt][2], a[mt][3], b2, b3);
                }
            }
        }
    };

    load_stage(0, 0); cpa_commit();
    load_stage(1, 1); cpa_commit();

    for (int t = 0; t < nt; t += 2) {
        cpa_wait<1>();
        __syncthreads();
        if (t + 2 < nt) load_stage(t + 2, (t + 2) & 3);
        cpa_commit();
        compute(t & 3);
        cpa_wait<1>();
        if (t + 3 < nt) load_stage(t + 3, (t + 3) & 3);
        cpa_commit();
        compute((t + 1) & 3);
    }

    const int g = lane >> 2, c = (lane & 3) << 1;
#pragma unroll
    for (int mt = 0; mt < 2; mt++)
#pragma unroll
        for (int ntl = 0; ntl < 4; ntl++) {
            int row = bm + wm + mt * 16 + g;
            int col = bn + wn + ntl * 8 + c;
            st2(&C[(size_t)row * N + col],       acc[mt][ntl][0], acc[mt][ntl][1]);
            st2(&C[(size_t)(row + 8) * N + col], acc[mt][ntl][2], acc[mt][ntl][3]);
        }
}

// ---------------- merged RMSNorm + RoPE (unchanged) ----------------
__global__ void norm_rope2(const float* __restrict__ Qraw, const float* __restrict__ Kraw,
                           const float* __restrict__ cosp, const float* __restrict__ sinp,
                           const float* __restrict__ qw, const float* __restrict__ kw,
                           __half* __restrict__ Qh, __half* __restrict__ Kh) {
    const int bid = blockIdx.x, d = threadIdx.x;
    const float* src; const float* wnorm; __half* dst;
    int row, h, nheads, pos;
    float outscale;
    if (bid < QLEN * H_HEADS) {
        row = bid >> 5; h = bid & 31; nheads = H_HEADS;
        src = Qraw; wnorm = qw; dst = Qh;
        pos = CTXLEN + row;
        outscale = 0.08838834764831845f * 1.4426950408889634f;
    } else {
        int b = bid - QLEN * H_HEADS;
        row = b >> 3; h = b & 7; nheads = KV_HEADS;
        src = Kraw; wnorm = kw; dst = Kh;
        pos = row;
        outscale = 1.0f;
    }
    const size_t base = (size_t)row * nheads * HEAD_DIM + h * HEAD_DIM;
    float x = src[base + d];
    float ss = x * x;
#pragma unroll
    for (int o = 16; o; o >>= 1) ss += __shfl_xor_sync(0xffffffffu, ss, o);
    __shared__ float ws[4];
    const int lane = d & 31, warp = d >> 5;
    if (lane == 0) ws[warp] = ss;
    __syncthreads();
    float sum = ws[0] + ws[1] + ws[2] + ws[3];
    float y = x * rsqrtf(sum * (1.0f / HEAD_DIM) + 1e-6f) * wnorm[d];
    __shared__ float ys[HEAD_DIM];
    ys[d] = y;
    __syncthreads();
    float partner = (d < 64) ? -ys[d + 64] : ys[d - 64];
    float o = y * cosp[pos * HEAD_DIM + d] + partner * sinp[pos * HEAD_DIM + d];
    dst[base + d] = __float2half(o * outscale);
}

// ---------------- flash attention: triple-buffered K/V, ONE barrier per tile ------
#define FPAD 136
#define F_SMEM (6 * 64 * FPAD * 2)     // 3 K bufs + 3 V bufs = 104,448 B; 2 CTAs/SM
__global__ __launch_bounds__(128, 2) void flash(const __half* __restrict__ Qh,
                                                const __half* __restrict__ Kh,
                                                const __half* __restrict__ Vh,
                                                __half* __restrict__ Oh) {
    extern __shared__ __align__(16) __half fsm[];
    __half* sK = fsm;                      // 3 * 64 * FPAD
    __half* sV = fsm + 3 * 64 * FPAD;      // 3 * 64 * FPAD
    const int tid = threadIdx.x, lane = tid & 31, w = tid >> 5;
    const int bx = gridDim.x - 1 - blockIdx.x;
    const int qb = bx << 6;
    const int h = blockIdx.y;
    const int kv = h >> 2;

    {
        const __half* Qp = Qh + (size_t)qb * QKDIM + h * HEAD_DIM;
        for (int i = tid; i < 64 * 16; i += 128) {
            int r = i >> 4, c = (i & 15) << 3;
            *(uint4*)&sK[r * FPAD + c] = *(const uint4*)&Qp[(size_t)r * QKDIM + c];
        }
    }
    __syncthreads();
    uint32_t qa[8][4];
#pragma unroll
    for (int kt = 0; kt < 8; kt++) {
        uint32_t ad = smem_u32(&sK[(w * 16 + (lane & 15)) * FPAD + kt * 16 + ((lane >> 4) << 3)]);
        ldsm4(qa[kt][0], qa[kt][1], qa[kt][2], qa[kt][3], ad);
    }
    __syncthreads();

    float O[16][4];
#pragma unroll
    for (int i = 0; i < 16; i++)
#pragma unroll
        for (int j = 0; j < 4; j++) O[i][j] = 0.f;
    float lacc[4] = {0.f, 0.f, 0.f, 0.f};
    float m0 = -1e30f, m1 = -1e30f;

    const int ntiles = 33 + bx;
    const __half* Kp = Kh + kv * HEAD_DIM;
    const __half* Vp = Vh + kv * HEAD_DIM;
    const int g = lane >> 2, c2 = (lane & 3) << 1;
    const uint32_t ONE2 = 0x3C003C00u;

    auto loadKV = [&](int t, int buf) {
        for (int i = tid; i < 64 * 16; i += 128) {
            int r = i >> 4, c = (i & 15) << 3;
            size_t go = (size_t)(t * 64 + r) * KVDIM + c;
            cpa16(smem_u32(&sK[(buf * 64 + r) * FPAD + c]), &Kp[go]);
            cpa16(smem_u32(&sV[(buf * 64 + r) * FPAD + c]), &Vp[go]);
        }
    };

    loadKV(0, 0);
    cpa_commit();

    int buf = 0, ldbuf = 1;
    for (int t = 0; t < ntiles; t++) {
        if (t + 1 < ntiles) loadKV(t + 1, ldbuf);
        cpa_commit();
        cpa_wait<1>();
        __syncthreads();                 // single barrier per tile
        const int krel0 = t * 64 - (CTXLEN + qb);

        if (krel0 <= w * 16 + 15) {
            float S[8][4];
#pragma unroll
            for (int i = 0; i < 8; i++)
#pragma unroll
                for (int j = 0; j < 4; j++) S[i][j] = 0.f;

#pragma unroll
            for (int kt = 0; kt < 8; kt++) {
#pragma unroll
                for (int n2 = 0; n2 < 4; n2++) {
                    uint32_t b0, b1, b2, b3;
                    uint32_t ad = smem_u32(&sK[(buf * 64 + n2 * 16 + ((lane >> 4) << 3) + (lane & 7)) * FPAD +
                                               kt * 16 + (((lane >> 3) & 1) << 3)]);
                    ldsm4(b0, b1, b2, b3, ad);
                    mma16816(S[2 * n2],     qa[kt][0], qa[kt][1], qa[kt][2], qa[kt][3], b0, b1);
                    mma16816(S[2 * n2 + 1], qa[kt][0], qa[kt][1], qa[kt][2], qa[kt][3], b2, b3);
                }
            }

            if (krel0 + 63 > w * 16) {
                int r0 = w * 16 + g - krel0, r1 = r0 + 8;
#pragma unroll
                for (int ntl = 0; ntl < 8; ntl++) {
                    int col = ntl * 8 + c2;
                    if (col     > r0) S[ntl][0] = -1e30f;
                    if (col + 1 > r0) S[ntl][1] = -1e30f;
                    if (col     > r1) S[ntl][2] = -1e30f;
                    if (col + 1 > r1) S[ntl][3] = -1e30f;
                }
            }

            float mt0 = -1e30f, mt1 = -1e30f;
#pragma unroll
            for (int ntl = 0; ntl < 8; ntl++) {
                mt0 = fmaxf(mt0, fmaxf(S[ntl][0], S[ntl][1]));
                mt1 = fmaxf(mt1, fmaxf(S[ntl][2], S[ntl][3]));
            }
            mt0 = fmaxf(mt0, __shfl_xor_sync(0xffffffffu, mt0, 1));
            mt0 = fmaxf(mt0, __shfl_xor_sync(0xffffffffu, mt0, 2));
            mt1 = fmaxf(mt1, __shfl_xor_sync(0xffffffffu, mt1, 1));
            mt1 = fmaxf(mt1, __shfl_xor_sync(0xffffffffu, mt1, 2));
            float mn0 = fmaxf(m0, mt0), mn1 = fmaxf(m1, mt1);

            uint32_t P[8][2];
#pragma unroll
            for (int ntl = 0; ntl < 8; ntl++) {
                P[ntl][0] = h2exp2(packh2(S[ntl][0] - mn0, S[ntl][1] - mn0));
                P[ntl][1] = h2exp2(packh2(S[ntl][2] - mn1, S[ntl][3] - mn1));
            }

            if (mn0 > m0 || mn1 > m1) {
                float a0 = exp2f(m0 - mn0), a1 = exp2f(m1 - mn1);
                lacc[0] *= a0; lacc[1] *= a0; lacc[2] *= a1; lacc[3] *= a1;
#pragma unroll
                for (int ntl = 0; ntl < 16; ntl++) {
                    O[ntl][0] *= a0; O[ntl][1] *= a0; O[ntl][2] *= a1; O[ntl][3] *= a1;
                }
            }
            m0 = mn0; m1 = mn1;

#pragma unroll
            for (int kc = 0; kc < 4; kc++) {
                uint32_t A0 = P[2 * kc][0],     A1 = P[2 * kc][1];
                uint32_t A2 = P[2 * kc + 1][0], A3 = P[2 * kc + 1][1];
                mma16816(lacc, A0, A1, A2, A3, ONE2, ONE2);
#pragma unroll
                for (int d2 = 0; d2 < 8; d2++) {
                    uint32_t v0, v1, v2, v3;
                    uint32_t ad = smem_u32(&sV[(buf * 64 + kc * 16 + (lane & 15)) * FPAD +
                                               d2 * 16 + ((lane >> 4) << 3)]);
                    ldsm4t(v0, v1, v2, v3, ad);
                    mma16816(O[2 * d2],     A0, A1, A2, A3, v0, v1);
                    mma16816(O[2 * d2 + 1], A0, A1, A2, A3, v2, v3);
                }
            }
        }
        buf = (buf == 2) ? 0 : buf + 1;
        ldbuf = (ldbuf == 2) ? 0 : ldbuf + 1;
    }

    float i0 = 1.f / lacc[0], i1 = 1.f / lacc[2];
    __half* Op = Oh + (size_t)(qb + w * 16) * QKDIM + h * HEAD_DIM;
#pragma unroll
    for (int ntl = 0; ntl < 16; ntl++) {
        int col = ntl * 8 + c2;
        *(__half2*)&Op[(size_t)g * QKDIM + col]       = __floats2half2_rn(O[ntl][0] * i0, O[ntl][1] * i0);
        *(__half2*)&Op[(size_t)(g + 8) * QKDIM + col] = __floats2half2_rn(O[ntl][2] * i1, O[ntl][3] * i1);
    }
}

// ---------------- launcher ----------------
extern "C" void kernel_launch(void* const* d_in, const int* in_sizes, int n_in,
                              void* d_out, int out_size) {
    const float* hidden = (const float*)d_in[0];
    const float* target = (const float*)d_in[1];
    const float* cosp   = (const float*)d_in[2];
    const float* sinp   = (const float*)d_in[3];
    const float* wq = (const float*)d_in[5];
    const float* wk = (const float*)d_in[6];
    const float* wv = (const float*)d_in[7];
    const float* wo = (const float*)d_in[8];
    const float* qw = (const float*)d_in[9];
    const float* kw = (const float*)d_in[10];
    float* out = (float*)d_out;

    __half *Xh, *Wqh, *Wkvh, *Woh, *Qh, *Kh, *Vh, *Oh;
    float *Qraw, *Kraw;
    cudaGetSymbolAddress((void**)&Xh, g_Xh);
    cudaGetSymbolAddress((void**)&Wqh, g_Wqh);
    cudaGetSymbolAddress((void**)&Wkvh, g_Wkvh);
    cudaGetSymbolAddress((void**)&Woh, g_Woh);
    cudaGetSymbolAddress((void**)&Qraw, g_Qraw);
    cudaGetSymbolAddress((void**)&Kraw, g_Kraw);
    cudaGetSymbolAddress((void**)&Qh, g_Qh);
    cudaGetSymbolAddress((void**)&Kh, g_Kh);
    cudaGetSymbolAddress((void**)&Vh, g_Vh);
    cudaGetSymbolAddress((void**)&Oh, g_Oh);

    cudaFuncSetAttribute((const void*)gemm_qkv, cudaFuncAttributeMaxDynamicSharedMemorySize, G_SMEM128);
    cudaFuncSetAttribute((const void*)gemm_o,   cudaFuncAttributeMaxDynamicSharedMemorySize, GO_SMEM);
    cudaFuncSetAttribute((const void*)flash,    cudaFuncAttributeMaxDynamicSharedMemorySize, F_SMEM);

    cvt6<<<1184, 256>>>(target, Xh, CTXLEN * HIDDEN / 8,
                        hidden, Xh + (size_t)CTXLEN * HIDDEN, QLEN * HIDDEN / 8,
                        wq, Wqh, QKDIM * HIDDEN / 8,
                        wk, Wkvh, KVDIM * HIDDEN / 8,
                        wv, Wkvh + (size_t)KVDIM * HIDDEN, KVDIM * HIDDEN / 8,
                        wo, Woh, HIDDEN * QKDIM / 8);

    gemm_qkv<<<640, 256, G_SMEM128>>>(Xh, Wqh, Wkvh, Qraw, Kraw, Vh);

    norm_rope2<<<QLEN * H_HEADS + TLEN * KV_HEADS, 128>>>(Qraw, Kraw, cosp, sinp, qw, kw, Qh, Kh);

    flash<<<dim3(QLEN / 64, H_HEADS), 128, F_SMEM>>>(Qh, Kh, Vh, Oh);

    gemm_o<<<dim3(HIDDEN / 64, QLEN / 128), 256, GO_SMEM>>>(Oh, Woh, out);
}

// round 16
// speedup vs baseline: 1.4037x; 1.4037x over previous
#include <cuda_runtime.h>
#include <cuda_fp16.h>
#include <cstdint>

#define H_HEADS   32
#define KV_HEADS  8
#define HEAD_DIM  128
#define HIDDEN    2048
#define QLEN      1024
#define CTXLEN    2048
#define TLEN      3072
#define QKDIM     (H_HEADS * HEAD_DIM)    // 4096
#define KVDIM     (KV_HEADS * HEAD_DIM)   // 1024

// ---------------- scratch ----------------
__device__ __half g_Xh  [TLEN * HIDDEN];
__device__ __half g_Wqh [QKDIM * HIDDEN];
__device__ __half g_Wkvh[2 * KVDIM * HIDDEN];
__device__ __half g_Woh [HIDDEN * QKDIM];
__device__ float  g_Qraw[QLEN * QKDIM];
__device__ float  g_Kraw[TLEN * KVDIM];
__device__ __half g_Qh  [QLEN * QKDIM];
__device__ __half g_Kh  [TLEN * KVDIM];
__device__ __half g_Vh  [TLEN * KVDIM];
__device__ __half g_Oh  [QLEN * QKDIM];

// ---------------- helpers ----------------
__device__ __forceinline__ uint32_t smem_u32(const void* p) {
    return (uint32_t)__cvta_generic_to_shared(p);
}
__device__ __forceinline__ void ldsm4(uint32_t& r0, uint32_t& r1, uint32_t& r2, uint32_t& r3, uint32_t a) {
    asm volatile("ldmatrix.sync.aligned.m8n8.x4.shared.b16 {%0,%1,%2,%3},[%4];\n"
                 : "=r"(r0), "=r"(r1), "=r"(r2), "=r"(r3) : "r"(a));
}
__device__ __forceinline__ void ldsm4t(uint32_t& r0, uint32_t& r1, uint32_t& r2, uint32_t& r3, uint32_t a) {
    asm volatile("ldmatrix.sync.aligned.m8n8.x4.trans.shared.b16 {%0,%1,%2,%3},[%4];\n"
                 : "=r"(r0), "=r"(r1), "=r"(r2), "=r"(r3) : "r"(a));
}
__device__ __forceinline__ void mma16816(float* c, uint32_t a0, uint32_t a1, uint32_t a2, uint32_t a3,
                                         uint32_t b0, uint32_t b1) {
    asm volatile("mma.sync.aligned.m16n8k16.row.col.f32.f16.f16.f32 "
                 "{%0,%1,%2,%3},{%4,%5,%6,%7},{%8,%9},{%0,%1,%2,%3};\n"
                 : "+f"(c[0]), "+f"(c[1]), "+f"(c[2]), "+f"(c[3])
                 : "r"(a0), "r"(a1), "r"(a2), "r"(a3), "r"(b0), "r"(b1));
}
__device__ __forceinline__ uint32_t packh2(float a, float b) {
    __half2 h = __floats2half2_rn(a, b);
    return *reinterpret_cast<uint32_t*>(&h);
}
__device__ __forceinline__ uint32_t h2exp2(uint32_t x) {
    uint32_t r;
    asm("ex2.approx.f16x2 %0, %1;" : "=r"(r) : "r"(x));
    return r;
}
__device__ __forceinline__ void cpa16(uint32_t dst, const void* src) {
    asm volatile("cp.async.cg.shared.global [%0],[%1],16;\n" :: "r"(dst), "l"(src));
}
__device__ __forceinline__ void cpa_commit() { asm volatile("cp.async.commit_group;\n"); }
template <int N> __device__ __forceinline__ void cpa_wait() {
    asm volatile("cp.async.wait_group %0;\n" :: "n"(N));
}
__device__ __forceinline__ void st2(float* p, float a, float b) { *(float2*)p = make_float2(a, b); }
__device__ __forceinline__ void st2(__half* p, float a, float b) { *(__half2*)p = __floats2half2_rn(a, b); }

// ---------------- fused fp32 -> fp16 conversion: 6 segments, 2x float4/thread ------
__global__ void cvt6(const float* s0, __half* d0, int n0, const float* s1, __half* d1, int n1,
                     const float* s2, __half* d2, int n2, const float* s3, __half* d3, int n3,
                     const float* s4, __half* d4, int n4c, const float* s5, __half* d5, int n5) {
    int total = n0 + n1 + n2 + n3 + n4c + n5;
    int stride = gridDim.x * blockDim.x;
    for (int i = blockIdx.x * blockDim.x + threadIdx.x; i < total; i += stride) {
        const float* s; __half* d; int j = i;
        if (j < n0) { s = s0; d = d0; }
        else if ((j -= n0) < n1) { s = s1; d = d1; }
        else if ((j -= n1) < n2) { s = s2; d = d2; }
        else if ((j -= n2) < n3) { s = s3; d = d3; }
        else if ((j -= n3) < n4c) { s = s4; d = d4; }
        else { j -= n4c; s = s5; d = d5; }
        float4 a = reinterpret_cast<const float4*>(s)[2 * j];
        float4 b = reinterpret_cast<const float4*>(s)[2 * j + 1];
        __half2 h0 = __floats2half2_rn(a.x, a.y), h1 = __floats2half2_rn(a.z, a.w);
        __half2 h2 = __floats2half2_rn(b.x, b.y), h3 = __floats2half2_rn(b.z, b.w);
        uint4 o;
        o.x = *(uint32_t*)&h0; o.y = *(uint32_t*)&h1; o.z = *(uint32_t*)&h2; o.w = *(uint32_t*)&h3;
        reinterpret_cast<uint4*>(d)[j] = o;
    }
}

// =========================================================================
// Merged Q+KV projection (round-12 proven version: 3 stages, 1 barrier/iter)
// =========================================================================
#define GSA 40
#define G_STAGES 3
#define G_ASTRIDE (128 * GSA)
#define G_SMEM128 (G_STAGES * G_ASTRIDE * 2 * 2)

__global__ __launch_bounds__(256, 2) void gemm_qkv(const __half* __restrict__ Xh,
                                                   const __half* __restrict__ Wqh,
                                                   const __half* __restrict__ Wkvh,
                                                   float* __restrict__ Qraw,
                                                   float* __restrict__ Kraw,
                                                   __half* __restrict__ Vh) {
    extern __shared__ __align__(16) __half gsm[];
    __half* As = gsm;
    __half* Bs = gsm + G_STAGES * G_ASTRIDE;
    const int tid = threadIdx.x, lane = tid & 31, w = tid >> 5;
    const int bid = blockIdx.x;
    const bool isQ = bid < 256;
    const __half* A;
    const __half* B;
    int bm, bn;
    if (isQ) {
        A = Xh + (size_t)CTXLEN * HIDDEN;
        B = Wqh;
        bm = (bid >> 5) << 7;
        bn = (bid & 31) << 7;
    } else {
        int b = bid - 256;
        A = Xh;
        B = Wkvh;
        bm = (b >> 4) << 7;
        bn = (b & 15) << 7;
    }
    const int wm = (w >> 1) << 5, wn = (w & 1) << 6;
    constexpr int K = HIDDEN;

    float acc[2][8][4];
#pragma unroll
    for (int i = 0; i < 2; i++)
#pragma unroll
        for (int j = 0; j < 8; j++)
#pragma unroll
            for (int k = 0; k < 4; k++) acc[i][j][k] = 0.f;

    const int r = tid >> 2, cch = (tid & 3) << 3;
    const int nt = K >> 5;

    auto load_stage = [&](int t, int s) {
        int k0 = t << 5;
        cpa16(smem_u32(&As[s * G_ASTRIDE + r * GSA + cch]),        &A[(size_t)(bm + r) * K + k0 + cch]);
        cpa16(smem_u32(&As[s * G_ASTRIDE + (r + 64) * GSA + cch]), &A[(size_t)(bm + r + 64) * K + k0 + cch]);
        cpa16(smem_u32(&Bs[s * G_ASTRIDE + r * GSA + cch]),        &B[(size_t)(bn + r) * K + k0 + cch]);
        cpa16(smem_u32(&Bs[s * G_ASTRIDE + (r + 64) * GSA + cch]), &B[(size_t)(bn + r + 64) * K + k0 + cch]);
    };

    load_stage(0, 0); cpa_commit();
    load_stage(1, 1); cpa_commit();

    int s_cur = 0, s_pre = 2;
    for (int t = 0; t < nt; t++) {
        cpa_wait<1>();
        __syncthreads();
        if (t + 2 < nt) load_stage(t + 2, s_pre);
        cpa_commit();

        const __half* as = As + s_cur * G_ASTRIDE;
        const __half* bs = Bs + s_cur * G_ASTRIDE;
#pragma unroll
        for (int kk = 0; kk < 2; kk++) {
            uint32_t a[2][4];
#pragma unroll
            for (int mt = 0; mt < 2; mt++) {
                uint32_t ad = smem_u32(&as[(wm + mt * 16 + (lane & 15)) * GSA + kk * 16 + ((lane >> 4) << 3)]);
                ldsm4(a[mt][0], a[mt][1], a[mt][2], a[mt][3], ad);
            }
#pragma unroll
            for (int n2 = 0; n2 < 4; n2++) {
                uint32_t b0, b1, b2, b3;
                uint32_t ad = smem_u32(&bs[(wn + n2 * 16 + ((lane >> 4) << 3) + (lane & 7)) * GSA +
                                           kk * 16 + (((lane >> 3) & 1) << 3)]);
                ldsm4(b0, b1, b2, b3, ad);
#pragma unroll
                for (int mt = 0; mt < 2; mt++) {
                    mma16816(acc[mt][2 * n2],     a[mt][0], a[mt][1], a[mt][2], a[mt][3], b0, b1);
                    mma16816(acc[mt][2 * n2 + 1], a[mt][0], a[mt][1], a[mt][2], a[mt][3], b2, b3);
                }
            }
        }
        s_pre = s_cur;
        s_cur = (s_cur == G_STAGES - 1) ? 0 : s_cur + 1;
    }

    const int g = lane >> 2, c = (lane & 3) << 1;
    if (isQ) {
#pragma unroll
        for (int mt = 0; mt < 2; mt++)
#pragma unroll
            for (int ntl = 0; ntl < 8; ntl++) {
                int row = bm + wm + mt * 16 + g;
                int col = bn + wn + ntl * 8 + c;
                st2(&Qraw[(size_t)row * QKDIM + col],       acc[mt][ntl][0], acc[mt][ntl][1]);
                st2(&Qraw[(size_t)(row + 8) * QKDIM + col], acc[mt][ntl][2], acc[mt][ntl][3]);
            }
    } else {
        const bool isK = bn < KVDIM;
        const int colbase = bn - (isK ? 0 : KVDIM) + wn;
#pragma unroll
        for (int mt = 0; mt < 2; mt++)
#pragma unroll
            for (int ntl = 0; ntl < 8; ntl++) {
                int row = bm + wm + mt * 16 + g;
                int col = colbase + ntl * 8 + c;
                if (isK) {
                    st2(&Kraw[(size_t)row * KVDIM + col],       acc[mt][ntl][0], acc[mt][ntl][1]);
                    st2(&Kraw[(size_t)(row + 8) * KVDIM + col], acc[mt][ntl][2], acc[mt][ntl][3]);
                } else {
                    st2(&Vh[(size_t)row * KVDIM + col],       acc[mt][ntl][0], acc[mt][ntl][1]);
                    st2(&Vh[(size_t)(row + 8) * KVDIM + col], acc[mt][ntl][2], acc[mt][ntl][3]);
                }
            }
    }
}

// ---------------- O-projection GEMM (round-12 proven version) ----------------
#define GO_SMEM (G_STAGES * (128 + 64) * GSA * 2)
__global__ __launch_bounds__(256, 2) void gemm_o(const __half* __restrict__ A,
                                                 const __half* __restrict__ B,
                                                 float* __restrict__ C) {
    constexpr int NB = 64, BSTRIDE = NB * GSA, K = QKDIM, N = HIDDEN;
    extern __shared__ __align__(16) __half gsm[];
    __half* As = gsm;
    __half* Bs = gsm + G_STAGES * G_ASTRIDE;
    const int tid = threadIdx.x, lane = tid & 31, w = tid >> 5;
    const int bm = blockIdx.y << 7, bn = blockIdx.x * NB;
    const int wm = (w >> 1) << 5, wn = (w & 1) << 5;

    float acc[2][4][4];
#pragma unroll
    for (int i = 0; i < 2; i++)
#pragma unroll
        for (int j = 0; j < 4; j++)
#pragma unroll
            for (int k = 0; k < 4; k++) acc[i][j][k] = 0.f;

    const int r = tid >> 2, cch = (tid & 3) << 3;
    const int nt = K >> 5;

    auto load_stage = [&](int t, int s) {
        int k0 = t << 5;
        cpa16(smem_u32(&As[s * G_ASTRIDE + r * GSA + cch]),        &A[(size_t)(bm + r) * K + k0 + cch]);
        cpa16(smem_u32(&As[s * G_ASTRIDE + (r + 64) * GSA + cch]), &A[(size_t)(bm + r + 64) * K + k0 + cch]);
        cpa16(smem_u32(&Bs[s * BSTRIDE + r * GSA + cch]),          &B[(size_t)(bn + r) * K + k0 + cch]);
    };

    load_stage(0, 0); cpa_commit();
    load_stage(1, 1); cpa_commit();

    int s_cur = 0, s_pre = 2;
    for (int t = 0; t < nt; t++) {
        cpa_wait<1>();
        __syncthreads();
        if (t + 2 < nt) load_stage(t + 2, s_pre);
        cpa_commit();

        const __half* as = As + s_cur * G_ASTRIDE;
        const __half* bs = Bs + s_cur * BSTRIDE;
#pragma unroll
        for (int kk = 0; kk < 2; kk++) {
            uint32_t a[2][4];
#pragma unroll
            for (int mt = 0; mt < 2; mt++) {
                uint32_t ad = smem_u32(&as[(wm + mt * 16 + (lane & 15)) * GSA + kk * 16 + ((lane >> 4) << 3)]);
                ldsm4(a[mt][0], a[mt][1], a[mt][2], a[mt][3], ad);
            }
#pragma unroll
            for (int n2 = 0; n2 < 2; n2++) {
                uint32_t b0, b1, b2, b3;
                uint32_t ad = smem_u32(&bs[(wn + n2 * 16 + ((lane >> 4) << 3) + (lane & 7)) * GSA +
                                           kk * 16 + (((lane >> 3) & 1) << 3)]);
                ldsm4(b0, b1, b2, b3, ad);
#pragma unroll
                for (int mt = 0; mt < 2; mt++) {
                    mma16816(acc[mt][2 * n2],     a[mt][0], a[mt][1], a[mt][2], a[mt][3], b0, b1);
                    mma16816(acc[mt][2 * n2 + 1], a[mt][0], a[mt][1], a[mt][2], a[mt][3], b2, b3);
                }
            }
        }
        s_pre = s_cur;
        s_cur = (s_cur == G_STAGES - 1) ? 0 : s_cur + 1;
    }

    const int g = lane >> 2, c = (lane & 3) << 1;
#pragma unroll
    for (int mt = 0; mt < 2; mt++)
#pragma unroll
        for (int ntl = 0; ntl < 4; ntl++) {
            int row = bm + wm + mt * 16 + g;
            int col = bn + wn + ntl * 8 + c;
            st2(&C[(size_t)row * N + col],       acc[mt][ntl][0], acc[mt][ntl][1]);
            st2(&C[(size_t)(row + 8) * N + col], acc[mt][ntl][2], acc[mt][ntl][3]);
        }
}

// ---------------- merged RMSNorm + RoPE (unchanged) ----------------
__global__ void norm_rope2(const float* __restrict__ Qraw, const float* __restrict__ Kraw,
                           const float* __restrict__ cosp, const float* __restrict__ sinp,
                           const float* __restrict__ qw, const float* __restrict__ kw,
                           __half* __restrict__ Qh, __half* __restrict__ Kh) {
    const int bid = blockIdx.x, d = threadIdx.x;
    const float* src; const float* wnorm; __half* dst;
    int row, h, nheads, pos;
    float outscale;
    if (bid < QLEN * H_HEADS) {
        row = bid >> 5; h = bid & 31; nheads = H_HEADS;
        src = Qraw; wnorm = qw; dst = Qh;
        pos = CTXLEN + row;
        outscale = 0.08838834764831845f * 1.4426950408889634f;
    } else {
        int b = bid - QLEN * H_HEADS;
        row = b >> 3; h = b & 7; nheads = KV_HEADS;
        src = Kraw; wnorm = kw; dst = Kh;
        pos = row;
        outscale = 1.0f;
    }
    const size_t base = (size_t)row * nheads * HEAD_DIM + h * HEAD_DIM;
    float x = src[base + d];
    float ss = x * x;
#pragma unroll
    for (int o = 16; o; o >>= 1) ss += __shfl_xor_sync(0xffffffffu, ss, o);
    __shared__ float ws[4];
    const int lane = d & 31, warp = d >> 5;
    if (lane == 0) ws[warp] = ss;
    __syncthreads();
    float sum = ws[0] + ws[1] + ws[2] + ws[3];
    float y = x * rsqrtf(sum * (1.0f / HEAD_DIM) + 1e-6f) * wnorm[d];
    __shared__ float ys[HEAD_DIM];
    ys[d] = y;
    __syncthreads();
    float partner = (d < 64) ? -ys[d + 64] : ys[d - 64];
    float o = y * cosp[pos * HEAD_DIM + d] + partner * sinp[pos * HEAD_DIM + d];
    dst[base + d] = __float2half(o * outscale);
}

// ---------------- flash attention: 64 q/CTA, 3 CTAs/SM, ONE barrier per tile ------
// Load for tile t+1 is issued AFTER the top barrier of tile t: every warp has
// finished reading buf (t+1)&1 (its last read was in iter t-1, before that
// barrier), so the bottom barrier is unnecessary. cpa_wait<0> at the top still
// overlaps the tile-t load with the whole of iteration t-1.
#define FPAD 136
#define F_SMEM (4 * 64 * FPAD * 2)     // 69,632 B; 3 CTAs = 208.9 KB / SM
__global__ __launch_bounds__(128, 3) void flash(const __half* __restrict__ Qh,
                                                const __half* __restrict__ Kh,
                                                const __half* __restrict__ Vh,
                                                __half* __restrict__ Oh) {
    extern __shared__ __align__(16) __half fsm[];
    __half* sK = fsm;
    __half* sV = fsm + 2 * 64 * FPAD;
    const int tid = threadIdx.x, lane = tid & 31, w = tid >> 5;
    const int bx = gridDim.x - 1 - blockIdx.x;   // heavy blocks first
    const int qb = bx << 6;                      // 64 queries
    const int h = blockIdx.y;
    const int kv = h >> 2;

    {
        const __half* Qp = Qh + (size_t)qb * QKDIM + h * HEAD_DIM;
        for (int i = tid; i < 64 * 16; i += 128) {
            int r = i >> 4, c = (i & 15) << 3;
            *(uint4*)&sK[r * FPAD + c] = *(const uint4*)&Qp[(size_t)r * QKDIM + c];
        }
    }
    __syncthreads();
    uint32_t qa[8][4];
#pragma unroll
    for (int kt = 0; kt < 8; kt++) {
        uint32_t ad = smem_u32(&sK[(w * 16 + (lane & 15)) * FPAD + kt * 16 + ((lane >> 4) << 3)]);
        ldsm4(qa[kt][0], qa[kt][1], qa[kt][2], qa[kt][3], ad);
    }
    __syncthreads();

    float O[16][4];
#pragma unroll
    for (int i = 0; i < 16; i++)
#pragma unroll
        for (int j = 0; j < 4; j++) O[i][j] = 0.f;
    float lacc[4] = {0.f, 0.f, 0.f, 0.f};
    float m0 = -1e30f, m1 = -1e30f;

    const int ntiles = 33 + bx;
    const __half* Kp = Kh + kv * HEAD_DIM;
    const __half* Vp = Vh + kv * HEAD_DIM;
    const int g = lane >> 2, c2 = (lane & 3) << 1;
    const uint32_t ONE2 = 0x3C003C00u;

    auto loadKV = [&](int t, int buf) {
        for (int i = tid; i < 64 * 16; i += 128) {
            int r = i >> 4, c = (i & 15) << 3;
            size_t go = (size_t)(t * 64 + r) * KVDIM + c;
            cpa16(smem_u32(&sK[(buf * 64 + r) * FPAD + c]), &Kp[go]);
            cpa16(smem_u32(&sV[(buf * 64 + r) * FPAD + c]), &Vp[go]);
        }
    };

    loadKV(0, 0);
    cpa_commit();

    for (int t = 0; t < ntiles; t++) {
        cpa_wait<0>();                  // tile t resident
        __syncthreads();                // single barrier per tile
        if (t + 1 < ntiles) loadKV(t + 1, (t + 1) & 1);   // safe: issued post-barrier
        cpa_commit();
        const int buf = t & 1;
        const int krel0 = t * 64 - (CTXLEN + qb);

        if (krel0 <= w * 16 + 15) {
            float S[8][4];
#pragma unroll
            for (int i = 0; i < 8; i++)
#pragma unroll
                for (int j = 0; j < 4; j++) S[i][j] = 0.f;

#pragma unroll
            for (int kt = 0; kt < 8; kt++) {
#pragma unroll
                for (int n2 = 0; n2 < 4; n2++) {
                    uint32_t b0, b1, b2, b3;
                    uint32_t ad = smem_u32(&sK[(buf * 64 + n2 * 16 + ((lane >> 4) << 3) + (lane & 7)) * FPAD +
                                               kt * 16 + (((lane >> 3) & 1) << 3)]);
                    ldsm4(b0, b1, b2, b3, ad);
                    mma16816(S[2 * n2],     qa[kt][0], qa[kt][1], qa[kt][2], qa[kt][3], b0, b1);
                    mma16816(S[2 * n2 + 1], qa[kt][0], qa[kt][1], qa[kt][2], qa[kt][3], b2, b3);
                }
            }

            if (krel0 + 63 > w * 16) {
                int r0 = w * 16 + g - krel0, r1 = r0 + 8;
#pragma unroll
                for (int ntl = 0; ntl < 8; ntl++) {
                    int col = ntl * 8 + c2;
                    if (col     > r0) S[ntl][0] = -1e30f;
                    if (col + 1 > r0) S[ntl][1] = -1e30f;
                    if (col     > r1) S[ntl][2] = -1e30f;
                    if (col + 1 > r1) S[ntl][3] = -1e30f;
                }
            }

            float mt0 = -1e30f, mt1 = -1e30f;
#pragma unroll
            for (int ntl = 0; ntl < 8; ntl++) {
                mt0 = fmaxf(mt0, fmaxf(S[ntl][0], S[ntl][1]));
                mt1 = fmaxf(mt1, fmaxf(S[ntl][2], S[ntl][3]));
            }
            mt0 = fmaxf(mt0, __shfl_xor_sync(0xffffffffu, mt0, 1));
            mt0 = fmaxf(mt0, __shfl_xor_sync(0xffffffffu, mt0, 2));
            mt1 = fmaxf(mt1, __shfl_xor_sync(0xffffffffu, mt1, 1));
            mt1 = fmaxf(mt1, __shfl_xor_sync(0xffffffffu, mt1, 2));
            float mn0 = fmaxf(m0, mt0), mn1 = fmaxf(m1, mt1);

            uint32_t P[8][2];
#pragma unroll
            for (int ntl = 0; ntl < 8; ntl++) {
                P[ntl][0] = h2exp2(packh2(S[ntl][0] - mn0, S[ntl][1] - mn0));
                P[ntl][1] = h2exp2(packh2(S[ntl][2] - mn1, S[ntl][3] - mn1));
            }

            if (mn0 > m0 || mn1 > m1) {
                float a0 = exp2f(m0 - mn0), a1 = exp2f(m1 - mn1);
                lacc[0] *= a0; lacc[1] *= a0; lacc[2] *= a1; lacc[3] *= a1;
#pragma unroll
                for (int ntl = 0; ntl < 16; ntl++) {
                    O[ntl][0] *= a0; O[ntl][1] *= a0; O[ntl][2] *= a1; O[ntl][3] *= a1;
                }
            }
            m0 = mn0; m1 = mn1;

#pragma unroll
            for (int kc = 0; kc < 4; kc++) {
                uint32_t A0 = P[2 * kc][0],     A1 = P[2 * kc][1];
                uint32_t A2 = P[2 * kc + 1][0], A3 = P[2 * kc + 1][1];
                mma16816(lacc, A0, A1, A2, A3, ONE2, ONE2);
#pragma unroll
                for (int d2 = 0; d2 < 8; d2++) {
                    uint32_t v0, v1, v2, v3;
                    uint32_t ad = smem_u32(&sV[(buf * 64 + kc * 16 + (lane & 15)) * FPAD +
                                               d2 * 16 + ((lane >> 4) << 3)]);
                    ldsm4t(v0, v1, v2, v3, ad);
                    mma16816(O[2 * d2],     A0, A1, A2, A3, v0, v1);
                    mma16816(O[2 * d2 + 1], A0, A1, A2, A3, v2, v3);
                }
            }
        }
        // no bottom barrier: next iteration's load is issued after the next top barrier
    }

    float i0 = 1.f / lacc[0], i1 = 1.f / lacc[2];
    __half* Op = Oh + (size_t)(qb + w * 16) * QKDIM + h * HEAD_DIM;
#pragma unroll
    for (int ntl = 0; ntl < 16; ntl++) {
        int col = ntl * 8 + c2;
        *(__half2*)&Op[(size_t)g * QKDIM + col]       = __floats2half2_rn(O[ntl][0] * i0, O[ntl][1] * i0);
        *(__half2*)&Op[(size_t)(g + 8) * QKDIM + col] = __floats2half2_rn(O[ntl][2] * i1, O[ntl][3] * i1);
    }
}

// ---------------- launcher ----------------
extern "C" void kernel_launch(void* const* d_in, const int* in_sizes, int n_in,
                              void* d_out, int out_size) {
    const float* hidden = (const float*)d_in[0];
    const float* target = (const float*)d_in[1];
    const float* cosp   = (const float*)d_in[2];
    const float* sinp   = (const float*)d_in[3];
    const float* wq = (const float*)d_in[5];
    const float* wk = (const float*)d_in[6];
    const float* wv = (const float*)d_in[7];
    const float* wo = (const float*)d_in[8];
    const float* qw = (const float*)d_in[9];
    const float* kw = (const float*)d_in[10];
    float* out = (float*)d_out;

    __half *Xh, *Wqh, *Wkvh, *Woh, *Qh, *Kh, *Vh, *Oh;
    float *Qraw, *Kraw;
    cudaGetSymbolAddress((void**)&Xh, g_Xh);
    cudaGetSymbolAddress((void**)&Wqh, g_Wqh);
    cudaGetSymbolAddress((void**)&Wkvh, g_Wkvh);
    cudaGetSymbolAddress((void**)&Woh, g_Woh);
    cudaGetSymbolAddress((void**)&Qraw, g_Qraw);
    cudaGetSymbolAddress((void**)&Kraw, g_Kraw);
    cudaGetSymbolAddress((void**)&Qh, g_Qh);
    cudaGetSymbolAddress((void**)&Kh, g_Kh);
    cudaGetSymbolAddress((void**)&Vh, g_Vh);
    cudaGetSymbolAddress((void**)&Oh, g_Oh);

    cudaFuncSetAttribute((const void*)gemm_qkv, cudaFuncAttributeMaxDynamicSharedMemorySize, G_SMEM128);
    cudaFuncSetAttribute((const void*)gemm_o,   cudaFuncAttributeMaxDynamicSharedMemorySize, GO_SMEM);
    cudaFuncSetAttribute((const void*)flash,    cudaFuncAttributeMaxDynamicSharedMemorySize, F_SMEM);

    cvt6<<<1184, 256>>>(target, Xh, CTXLEN * HIDDEN / 8,
                        hidden, Xh + (size_t)CTXLEN * HIDDEN, QLEN * HIDDEN / 8,
                        wq, Wqh, QKDIM * HIDDEN / 8,
                        wk, Wkvh, KVDIM * HIDDEN / 8,
                        wv, Wkvh + (size_t)KVDIM * HIDDEN, KVDIM * HIDDEN / 8,
                        wo, Woh, HIDDEN * QKDIM / 8);

    gemm_qkv<<<640, 256, G_SMEM128>>>(Xh, Wqh, Wkvh, Qraw, Kraw, Vh);

    norm_rope2<<<QLEN * H_HEADS + TLEN * KV_HEADS, 128>>>(Qraw, Kraw, cosp, sinp, qw, kw, Qh, Kh);

    flash<<<dim3(QLEN / 64, H_HEADS), 128, F_SMEM>>>(Qh, Kh, Vh, Oh);

    gemm_o<<<dim3(HIDDEN / 64, QLEN / 128), 256, GO_SMEM>>>(Oh, Woh, out);
}

// round 17
// speedup vs baseline: 1.4539x; 1.0358x over previous
#include <cuda_runtime.h>
#include <cuda_fp16.h>
#include <cstdint>

#define H_HEADS   32
#define KV_HEADS  8
#define HEAD_DIM  128
#define HIDDEN    2048
#define QLEN      1024
#define CTXLEN    2048
#define TLEN      3072
#define QKDIM     (H_HEADS * HEAD_DIM)    // 4096
#define KVDIM     (KV_HEADS * HEAD_DIM)   // 1024

// ---------------- scratch ----------------
__device__ __half g_Xh  [TLEN * HIDDEN];
__device__ __half g_Wqh [QKDIM * HIDDEN];
__device__ __half g_Wkvh[2 * KVDIM * HIDDEN];
__device__ __half g_Woh [HIDDEN * QKDIM];
__device__ float  g_Qraw[QLEN * QKDIM];
__device__ float  g_Kraw[TLEN * KVDIM];
__device__ __half g_Qh  [QLEN * QKDIM];
__device__ __half g_Kh  [TLEN * KVDIM];
__device__ __half g_Vh  [TLEN * KVDIM];
__device__ __half g_Oh  [QLEN * QKDIM];

// ---------------- helpers ----------------
__device__ __forceinline__ uint32_t smem_u32(const void* p) {
    return (uint32_t)__cvta_generic_to_shared(p);
}
__device__ __forceinline__ void ldsm4(uint32_t& r0, uint32_t& r1, uint32_t& r2, uint32_t& r3, uint32_t a) {
    asm volatile("ldmatrix.sync.aligned.m8n8.x4.shared.b16 {%0,%1,%2,%3},[%4];\n"
                 : "=r"(r0), "=r"(r1), "=r"(r2), "=r"(r3) : "r"(a));
}
__device__ __forceinline__ void ldsm4t(uint32_t& r0, uint32_t& r1, uint32_t& r2, uint32_t& r3, uint32_t a) {
    asm volatile("ldmatrix.sync.aligned.m8n8.x4.trans.shared.b16 {%0,%1,%2,%3},[%4];\n"
                 : "=r"(r0), "=r"(r1), "=r"(r2), "=r"(r3) : "r"(a));
}
__device__ __forceinline__ void mma16816(float* c, uint32_t a0, uint32_t a1, uint32_t a2, uint32_t a3,
                                         uint32_t b0, uint32_t b1) {
    asm volatile("mma.sync.aligned.m16n8k16.row.col.f32.f16.f16.f32 "
                 "{%0,%1,%2,%3},{%4,%5,%6,%7},{%8,%9},{%0,%1,%2,%3};\n"
                 : "+f"(c[0]), "+f"(c[1]), "+f"(c[2]), "+f"(c[3])
                 : "r"(a0), "r"(a1), "r"(a2), "r"(a3), "r"(b0), "r"(b1));
}
__device__ __forceinline__ uint32_t packh2(float a, float b) {
    __half2 h = __floats2half2_rn(a, b);
    return *reinterpret_cast<uint32_t*>(&h);
}
__device__ __forceinline__ uint32_t h2exp2(uint32_t x) {
    uint32_t r;
    asm("ex2.approx.f16x2 %0, %1;" : "=r"(r) : "r"(x));
    return r;
}
__device__ __forceinline__ void cpa16(uint32_t dst, const void* src) {
    asm volatile("cp.async.cg.shared.global [%0],[%1],16;\n" :: "r"(dst), "l"(src));
}
__device__ __forceinline__ void cpa_commit() { asm volatile("cp.async.commit_group;\n"); }
template <int N> __device__ __forceinline__ void cpa_wait() {
    asm volatile("cp.async.wait_group %0;\n" :: "n"(N));
}
__device__ __forceinline__ void st2(float* p, float a, float b) { *(float2*)p = make_float2(a, b); }
__device__ __forceinline__ void st2(__half* p, float a, float b) { *(__half2*)p = __floats2half2_rn(a, b); }

// ---------------- fused fp32 -> fp16 conversion ----------------
__global__ void cvt6(const float* s0, __half* d0, int n0, const float* s1, __half* d1, int n1,
                     const float* s2, __half* d2, int n2, const float* s3, __half* d3, int n3,
                     const float* s4, __half* d4, int n4c, const float* s5, __half* d5, int n5) {
    int total = n0 + n1 + n2 + n3 + n4c + n5;
    int stride = gridDim.x * blockDim.x;
    for (int i = blockIdx.x * blockDim.x + threadIdx.x; i < total; i += stride) {
        const float* s; __half* d; int j = i;
        if (j < n0) { s = s0; d = d0; }
        else if ((j -= n0) < n1) { s = s1; d = d1; }
        else if ((j -= n1) < n2) { s = s2; d = d2; }
        else if ((j -= n2) < n3) { s = s3; d = d3; }
        else if ((j -= n3) < n4c) { s = s4; d = d4; }
        else { j -= n4c; s = s5; d = d5; }
        float4 a = reinterpret_cast<const float4*>(s)[2 * j];
        float4 b = reinterpret_cast<const float4*>(s)[2 * j + 1];
        __half2 h0 = __floats2half2_rn(a.x, a.y), h1 = __floats2half2_rn(a.z, a.w);
        __half2 h2 = __floats2half2_rn(b.x, b.y), h3 = __floats2half2_rn(b.z, b.w);
        uint4 o;
        o.x = *(uint32_t*)&h0; o.y = *(uint32_t*)&h1; o.z = *(uint32_t*)&h2; o.w = *(uint32_t*)&h3;
        reinterpret_cast<uint4*>(d)[j] = o;
    }
}

// =========================================================================
// Merged Q+KV projection: 128x128x32 CTA tile, 128 threads, 4 warps,
// 64x64 warp tile (32 MMAs per 8 ldsm), 3-stage cp.async, 1 barrier/iter.
// =========================================================================
#define GSA 40
#define G_STAGES 3
#define G_ASTRIDE (128 * GSA)
#define G_SMEM128 (G_STAGES * G_ASTRIDE * 2 * 2)

__global__ __launch_bounds__(128, 2) void gemm_qkv(const __half* __restrict__ Xh,
                                                   const __half* __restrict__ Wqh,
                                                   const __half* __restrict__ Wkvh,
                                                   float* __restrict__ Qraw,
                                                   float* __restrict__ Kraw,
                                                   __half* __restrict__ Vh) {
    extern __shared__ __align__(16) __half gsm[];
    __half* As = gsm;
    __half* Bs = gsm + G_STAGES * G_ASTRIDE;
    const int tid = threadIdx.x, lane = tid & 31, w = tid >> 5;
    const int bid = blockIdx.x;
    const bool isQ = bid < 256;
    const __half* A;
    const __half* B;
    int bm, bn;
    if (isQ) {
        A = Xh + (size_t)CTXLEN * HIDDEN;
        B = Wqh;
        bm = (bid >> 5) << 7;
        bn = (bid & 31) << 7;
    } else {
        int b = bid - 256;
        A = Xh;
        B = Wkvh;
        bm = (b >> 4) << 7;
        bn = (b & 15) << 7;
    }
    const int wm = (w >> 1) << 6, wn = (w & 1) << 6;   // 64x64 warp tiles, 2x2 layout
    constexpr int K = HIDDEN;

    float acc[4][8][4];                                 // 4 m16 x 8 n8
#pragma unroll
    for (int i = 0; i < 4; i++)
#pragma unroll
        for (int j = 0; j < 8; j++)
#pragma unroll
            for (int k = 0; k < 4; k++) acc[i][j][k] = 0.f;

    const int r = tid >> 2, cch = (tid & 3) << 3;       // 32 rows per pass, 4 passes
    const int nt = K >> 5;

    auto load_stage = [&](int t, int s) {
        int k0 = t << 5;
#pragma unroll
        for (int p = 0; p < 4; p++) {
            int rr = r + p * 32;
            cpa16(smem_u32(&As[s * G_ASTRIDE + rr * GSA + cch]), &A[(size_t)(bm + rr) * K + k0 + cch]);
            cpa16(smem_u32(&Bs[s * G_ASTRIDE + rr * GSA + cch]), &B[(size_t)(bn + rr) * K + k0 + cch]);
        }
    };

    load_stage(0, 0); cpa_commit();
    load_stage(1, 1); cpa_commit();

    int s_cur = 0, s_pre = 2;
    for (int t = 0; t < nt; t++) {
        cpa_wait<1>();
        __syncthreads();
        if (t + 2 < nt) load_stage(t + 2, s_pre);
        cpa_commit();

        const __half* as = As + s_cur * G_ASTRIDE;
        const __half* bs = Bs + s_cur * G_ASTRIDE;
#pragma unroll
        for (int kk = 0; kk < 2; kk++) {
            uint32_t a[4][4];
#pragma unroll
            for (int mt = 0; mt < 4; mt++) {
                uint32_t ad = smem_u32(&as[(wm + mt * 16 + (lane & 15)) * GSA + kk * 16 + ((lane >> 4) << 3)]);
                ldsm4(a[mt][0], a[mt][1], a[mt][2], a[mt][3], ad);
            }
#pragma unroll
            for (int n2 = 0; n2 < 4; n2++) {
                uint32_t b0, b1, b2, b3;
                uint32_t ad = smem_u32(&bs[(wn + n2 * 16 + ((lane >> 4) << 3) + (lane & 7)) * GSA +
                                           kk * 16 + (((lane >> 3) & 1) << 3)]);
                ldsm4(b0, b1, b2, b3, ad);
#pragma unroll
                for (int mt = 0; mt < 4; mt++) {
                    mma16816(acc[mt][2 * n2],     a[mt][0], a[mt][1], a[mt][2], a[mt][3], b0, b1);
                    mma16816(acc[mt][2 * n2 + 1], a[mt][0], a[mt][1], a[mt][2], a[mt][3], b2, b3);
                }
            }
        }
        s_pre = s_cur;
        s_cur = (s_cur == G_STAGES - 1) ? 0 : s_cur + 1;
    }

    const int g = lane >> 2, c = (lane & 3) << 1;
    if (isQ) {
#pragma unroll
        for (int mt = 0; mt < 4; mt++)
#pragma unroll
            for (int ntl = 0; ntl < 8; ntl++) {
                int row = bm + wm + mt * 16 + g;
                int col = bn + wn + ntl * 8 + c;
                st2(&Qraw[(size_t)row * QKDIM + col],       acc[mt][ntl][0], acc[mt][ntl][1]);
                st2(&Qraw[(size_t)(row + 8) * QKDIM + col], acc[mt][ntl][2], acc[mt][ntl][3]);
            }
    } else {
        const bool isK = bn < KVDIM;
        const int colbase = bn - (isK ? 0 : KVDIM) + wn;
#pragma unroll
        for (int mt = 0; mt < 4; mt++)
#pragma unroll
            for (int ntl = 0; ntl < 8; ntl++) {
                int row = bm + wm + mt * 16 + g;
                int col = colbase + ntl * 8 + c;
                if (isK) {
                    st2(&Kraw[(size_t)row * KVDIM + col],       acc[mt][ntl][0], acc[mt][ntl][1]);
                    st2(&Kraw[(size_t)(row + 8) * KVDIM + col], acc[mt][ntl][2], acc[mt][ntl][3]);
                } else {
                    st2(&Vh[(size_t)row * KVDIM + col],       acc[mt][ntl][0], acc[mt][ntl][1]);
                    st2(&Vh[(size_t)(row + 8) * KVDIM + col], acc[mt][ntl][2], acc[mt][ntl][3]);
                }
            }
    }
}

// ---------------- O-projection GEMM (round-12 proven version) ----------------
#define GO_SMEM (G_STAGES * (128 + 64) * GSA * 2)
__global__ __launch_bounds__(256, 2) void gemm_o(const __half* __restrict__ A,
                                                 const __half* __restrict__ B,
                                                 float* __restrict__ C) {
    constexpr int NB = 64, BSTRIDE = NB * GSA, K = QKDIM, N = HIDDEN;
    extern __shared__ __align__(16) __half gsm[];
    __half* As = gsm;
    __half* Bs = gsm + G_STAGES * G_ASTRIDE;
    const int tid = threadIdx.x, lane = tid & 31, w = tid >> 5;
    const int bm = blockIdx.y << 7, bn = blockIdx.x * NB;
    const int wm = (w >> 1) << 5, wn = (w & 1) << 5;

    float acc[2][4][4];
#pragma unroll
    for (int i = 0; i < 2; i++)
#pragma unroll
        for (int j = 0; j < 4; j++)
#pragma unroll
            for (int k = 0; k < 4; k++) acc[i][j][k] = 0.f;

    const int r = tid >> 2, cch = (tid & 3) << 3;
    const int nt = K >> 5;

    auto load_stage = [&](int t, int s) {
        int k0 = t << 5;
        cpa16(smem_u32(&As[s * G_ASTRIDE + r * GSA + cch]),        &A[(size_t)(bm + r) * K + k0 + cch]);
        cpa16(smem_u32(&As[s * G_ASTRIDE + (r + 64) * GSA + cch]), &A[(size_t)(bm + r + 64) * K + k0 + cch]);
        cpa16(smem_u32(&Bs[s * BSTRIDE + r * GSA + cch]),          &B[(size_t)(bn + r) * K + k0 + cch]);
    };

    load_stage(0, 0); cpa_commit();
    load_stage(1, 1); cpa_commit();

    int s_cur = 0, s_pre = 2;
    for (int t = 0; t < nt; t++) {
        cpa_wait<1>();
        __syncthreads();
        if (t + 2 < nt) load_stage(t + 2, s_pre);
        cpa_commit();

        const __half* as = As + s_cur * G_ASTRIDE;
        const __half* bs = Bs + s_cur * BSTRIDE;
#pragma unroll
        for (int kk = 0; kk < 2; kk++) {
            uint32_t a[2][4];
#pragma unroll
            for (int mt = 0; mt < 2; mt++) {
                uint32_t ad = smem_u32(&as[(wm + mt * 16 + (lane & 15)) * GSA + kk * 16 + ((lane >> 4) << 3)]);
                ldsm4(a[mt][0], a[mt][1], a[mt][2], a[mt][3], ad);
            }
#pragma unroll
            for (int n2 = 0; n2 < 2; n2++) {
                uint32_t b0, b1, b2, b3;
                uint32_t ad = smem_u32(&bs[(wn + n2 * 16 + ((lane >> 4) << 3) + (lane & 7)) * GSA +
                                           kk * 16 + (((lane >> 3) & 1) << 3)]);
                ldsm4(b0, b1, b2, b3, ad);
#pragma unroll
                for (int mt = 0; mt < 2; mt++) {
                    mma16816(acc[mt][2 * n2],     a[mt][0], a[mt][1], a[mt][2], a[mt][3], b0, b1);
                    mma16816(acc[mt][2 * n2 + 1], a[mt][0], a[mt][1], a[mt][2], a[mt][3], b2, b3);
                }
            }
        }
        s_pre = s_cur;
        s_cur = (s_cur == G_STAGES - 1) ? 0 : s_cur + 1;
    }

    const int g = lane >> 2, c = (lane & 3) << 1;
#pragma unroll
    for (int mt = 0; mt < 2; mt++)
#pragma unroll
        for (int ntl = 0; ntl < 4; ntl++) {
            int row = bm + wm + mt * 16 + g;
            int col = bn + wn + ntl * 8 + c;
            st2(&C[(size_t)row * N + col],       acc[mt][ntl][0], acc[mt][ntl][1]);
            st2(&C[(size_t)(row + 8) * N + col], acc[mt][ntl][2], acc[mt][ntl][3]);
        }
}

// ---------------- merged RMSNorm + RoPE (unchanged) ----------------
__global__ void norm_rope2(const float* __restrict__ Qraw, const float* __restrict__ Kraw,
                           const float* __restrict__ cosp, const float* __restrict__ sinp,
                           const float* __restrict__ qw, const float* __restrict__ kw,
                           __half* __restrict__ Qh, __half* __restrict__ Kh) {
    const int bid = blockIdx.x, d = threadIdx.x;
    const float* src; const float* wnorm; __half* dst;
    int row, h, nheads, pos;
    float outscale;
    if (bid < QLEN * H_HEADS) {
        row = bid >> 5; h = bid & 31; nheads = H_HEADS;
        src = Qraw; wnorm = qw; dst = Qh;
        pos = CTXLEN + row;
        outscale = 0.08838834764831845f * 1.4426950408889634f;
    } else {
        int b = bid - QLEN * H_HEADS;
        row = b >> 3; h = b & 7; nheads = KV_HEADS;
        src = Kraw; wnorm = kw; dst = Kh;
        pos = row;
        outscale = 1.0f;
    }
    const size_t base = (size_t)row * nheads * HEAD_DIM + h * HEAD_DIM;
    float x = src[base + d];
    float ss = x * x;
#pragma unroll
    for (int o = 16; o; o >>= 1) ss += __shfl_xor_sync(0xffffffffu, ss, o);
    __shared__ float ws[4];
    const int lane = d & 31, warp = d >> 5;
    if (lane == 0) ws[warp] = ss;
    __syncthreads();
    float sum = ws[0] + ws[1] + ws[2] + ws[3];
    float y = x * rsqrtf(sum * (1.0f / HEAD_DIM) + 1e-6f) * wnorm[d];
    __shared__ float ys[HEAD_DIM];
    ys[d] = y;
    __syncthreads();
    float partner = (d < 64) ? -ys[d + 64] : ys[d - 64];
    float o = y * cosp[pos * HEAD_DIM + d] + partner * sinp[pos * HEAD_DIM + d];
    dst[base + d] = __float2half(o * outscale);
}

// ---------------- flash attention (exact round-12 version: 171 us proven) ----------
#define FPAD 136
#define F_SMEM (4 * 64 * FPAD * 2)
__global__ __launch_bounds__(128, 3) void flash(const __half* __restrict__ Qh,
                                                const __half* __restrict__ Kh,
                                                const __half* __restrict__ Vh,
                                                __half* __restrict__ Oh) {
    extern __shared__ __align__(16) __half fsm[];
    __half* sK = fsm;
    __half* sV = fsm + 2 * 64 * FPAD;
    const int tid = threadIdx.x, lane = tid & 31, w = tid >> 5;
    const int bx = gridDim.x - 1 - blockIdx.x;
    const int qb = bx << 6;
    const int h = blockIdx.y;
    const int kv = h >> 2;

    {
        const __half* Qp = Qh + (size_t)qb * QKDIM + h * HEAD_DIM;
        for (int i = tid; i < 64 * 16; i += 128) {
            int r = i >> 4, c = (i & 15) << 3;
            *(uint4*)&sK[r * FPAD + c] = *(const uint4*)&Qp[(size_t)r * QKDIM + c];
        }
    }
    __syncthreads();
    uint32_t qa[8][4];
#pragma unroll
    for (int kt = 0; kt < 8; kt++) {
        uint32_t ad = smem_u32(&sK[(w * 16 + (lane & 15)) * FPAD + kt * 16 + ((lane >> 4) << 3)]);
        ldsm4(qa[kt][0], qa[kt][1], qa[kt][2], qa[kt][3], ad);
    }
    __syncthreads();

    float O[16][4];
#pragma unroll
    for (int i = 0; i < 16; i++)
#pragma unroll
        for (int j = 0; j < 4; j++) O[i][j] = 0.f;
    float lacc[4] = {0.f, 0.f, 0.f, 0.f};
    float m0 = -1e30f, m1 = -1e30f;

    const int ntiles = 33 + bx;
    const __half* Kp = Kh + kv * HEAD_DIM;
    const __half* Vp = Vh + kv * HEAD_DIM;
    const int g = lane >> 2, c2 = (lane & 3) << 1;
    const uint32_t ONE2 = 0x3C003C00u;

    auto loadKV = [&](int t, int buf) {
        for (int i = tid; i < 64 * 16; i += 128) {
            int r = i >> 4, c = (i & 15) << 3;
            size_t go = (size_t)(t * 64 + r) * KVDIM + c;
            cpa16(smem_u32(&sK[(buf * 64 + r) * FPAD + c]), &Kp[go]);
            cpa16(smem_u32(&sV[(buf * 64 + r) * FPAD + c]), &Vp[go]);
        }
    };

    loadKV(0, 0);
    cpa_commit();

    for (int t = 0; t < ntiles; t++) {
        if (t + 1 < ntiles) loadKV(t + 1, (t + 1) & 1);
        cpa_commit();
        cpa_wait<1>();
        __syncthreads();
        const int buf = t & 1;
        const int krel0 = t * 64 - (CTXLEN + qb);

        if (krel0 <= w * 16 + 15) {
            float S[8][4];
#pragma unroll
            for (int i = 0; i < 8; i++)
#pragma unroll
                for (int j = 0; j < 4; j++) S[i][j] = 0.f;

#pragma unroll
            for (int kt = 0; kt < 8; kt++) {
#pragma unroll
                for (int n2 = 0; n2 < 4; n2++) {
                    uint32_t b0, b1, b2, b3;
                    uint32_t ad = smem_u32(&sK[(buf * 64 + n2 * 16 + ((lane >> 4) << 3) + (lane & 7)) * FPAD +
                                               kt * 16 + (((lane >> 3) & 1) << 3)]);
                    ldsm4(b0, b1, b2, b3, ad);
                    mma16816(S[2 * n2],     qa[kt][0], qa[kt][1], qa[kt][2], qa[kt][3], b0, b1);
                    mma16816(S[2 * n2 + 1], qa[kt][0], qa[kt][1], qa[kt][2], qa[kt][3], b2, b3);
                }
            }

            if (krel0 + 63 > w * 16) {
                int r0 = w * 16 + g - krel0, r1 = r0 + 8;
#pragma unroll
                for (int ntl = 0; ntl < 8; ntl++) {
                    int col = ntl * 8 + c2;
                    if (col     > r0) S[ntl][0] = -1e30f;
                    if (col + 1 > r0) S[ntl][1] = -1e30f;
                    if (col     > r1) S[ntl][2] = -1e30f;
                    if (col + 1 > r1) S[ntl][3] = -1e30f;
                }
            }

            float mt0 = -1e30f, mt1 = -1e30f;
#pragma unroll
            for (int ntl = 0; ntl < 8; ntl++) {
                mt0 = fmaxf(mt0, fmaxf(S[ntl][0], S[ntl][1]));
                mt1 = fmaxf(mt1, fmaxf(S[ntl][2], S[ntl][3]));
            }
            mt0 = fmaxf(mt0, __shfl_xor_sync(0xffffffffu, mt0, 1));
            mt0 = fmaxf(mt0, __shfl_xor_sync(0xffffffffu, mt0, 2));
            mt1 = fmaxf(mt1, __shfl_xor_sync(0xffffffffu, mt1, 1));
            mt1 = fmaxf(mt1, __shfl_xor_sync(0xffffffffu, mt1, 2));
            float mn0 = fmaxf(m0, mt0), mn1 = fmaxf(m1, mt1);

            uint32_t P[8][2];
#pragma unroll
            for (int ntl = 0; ntl < 8; ntl++) {
                P[ntl][0] = h2exp2(packh2(S[ntl][0] - mn0, S[ntl][1] - mn0));
                P[ntl][1] = h2exp2(packh2(S[ntl][2] - mn1, S[ntl][3] - mn1));
            }

            if (mn0 > m0 || mn1 > m1) {
                float a0 = exp2f(m0 - mn0), a1 = exp2f(m1 - mn1);
                lacc[0] *= a0; lacc[1] *= a0; lacc[2] *= a1; lacc[3] *= a1;
#pragma unroll
                for (int ntl = 0; ntl < 16; ntl++) {
                    O[ntl][0] *= a0; O[ntl][1] *= a0; O[ntl][2] *= a1; O[ntl][3] *= a1;
                }
            }
            m0 = mn0; m1 = mn1;

#pragma unroll
            for (int kc = 0; kc < 4; kc++) {
                uint32_t A0 = P[2 * kc][0],     A1 = P[2 * kc][1];
                uint32_t A2 = P[2 * kc + 1][0], A3 = P[2 * kc + 1][1];
                mma16816(lacc, A0, A1, A2, A3, ONE2, ONE2);
#pragma unroll
                for (int d2 = 0; d2 < 8; d2++) {
                    uint32_t v0, v1, v2, v3;
                    uint32_t ad = smem_u32(&sV[(buf * 64 + kc * 16 + (lane & 15)) * FPAD +
                                               d2 * 16 + ((lane >> 4) << 3)]);
                    ldsm4t(v0, v1, v2, v3, ad);
                    mma16816(O[2 * d2],     A0, A1, A2, A3, v0, v1);
                    mma16816(O[2 * d2 + 1], A0, A1, A2, A3, v2, v3);
                }
            }
        }
        __syncthreads();
    }

    float i0 = 1.f / lacc[0], i1 = 1.f / lacc[2];
    __half* Op = Oh + (size_t)(qb + w * 16) * QKDIM + h * HEAD_DIM;
#pragma unroll
    for (int ntl = 0; ntl < 16; ntl++) {
        int col = ntl * 8 + c2;
        *(__half2*)&Op[(size_t)g * QKDIM + col]       = __floats2half2_rn(O[ntl][0] * i0, O[ntl][1] * i0);
        *(__half2*)&Op[(size_t)(g + 8) * QKDIM + col] = __floats2half2_rn(O[ntl][2] * i1, O[ntl][3] * i1);
    }
}

// ---------------- launcher ----------------
extern "C" void kernel_launch(void* const* d_in, const int* in_sizes, int n_in,
                              void* d_out, int out_size) {
    const float* hidden = (const float*)d_in[0];
    const float* target = (const float*)d_in[1];
    const float* cosp   = (const float*)d_in[2];
    const float* sinp   = (const float*)d_in[3];
    const float* wq = (const float*)d_in[5];
    const float* wk = (const float*)d_in[6];
    const float* wv = (const float*)d_in[7];
    const float* wo = (const float*)d_in[8];
    const float* qw = (const float*)d_in[9];
    const float* kw = (const float*)d_in[10];
    float* out = (float*)d_out;

    __half *Xh, *Wqh, *Wkvh, *Woh, *Qh, *Kh, *Vh, *Oh;
    float *Qraw, *Kraw;
    cudaGetSymbolAddress((void**)&Xh, g_Xh);
    cudaGetSymbolAddress((void**)&Wqh, g_Wqh);
    cudaGetSymbolAddress((void**)&Wkvh, g_Wkvh);
    cudaGetSymbolAddress((void**)&Woh, g_Woh);
    cudaGetSymbolAddress((void**)&Qraw, g_Qraw);
    cudaGetSymbolAddress((void**)&Kraw, g_Kraw);
    cudaGetSymbolAddress((void**)&Qh, g_Qh);
    cudaGetSymbolAddress((void**)&Kh, g_Kh);
    cudaGetSymbolAddress((void**)&Vh, g_Vh);
    cudaGetSymbolAddress((void**)&Oh, g_Oh);

    cudaFuncSetAttribute((const void*)gemm_qkv, cudaFuncAttributeMaxDynamicSharedMemorySize, G_SMEM128);
    cudaFuncSetAttribute((const void*)gemm_o,   cudaFuncAttributeMaxDynamicSharedMemorySize, GO_SMEM);
    cudaFuncSetAttribute((const void*)flash,    cudaFuncAttributeMaxDynamicSharedMemorySize, F_SMEM);

    cvt6<<<1184, 256>>>(target, Xh, CTXLEN * HIDDEN / 8,
                        hidden, Xh + (size_t)CTXLEN * HIDDEN, QLEN * HIDDEN / 8,
                        wq, Wqh, QKDIM * HIDDEN / 8,
                        wk, Wkvh, KVDIM * HIDDEN / 8,
                        wv, Wkvh + (size_t)KVDIM * HIDDEN, KVDIM * HIDDEN / 8,
                        wo, Woh, HIDDEN * QKDIM / 8);

    // 128 threads, 4 warps, 64x64 warp tiles
    gemm_qkv<<<640, 128, G_SMEM128>>>(Xh, Wqh, Wkvh, Qraw, Kraw, Vh);

    norm_rope2<<<QLEN * H_HEADS + TLEN * KV_HEADS, 128>>>(Qraw, Kraw, cosp, sinp, qw, kw, Qh, Kh);

    flash<<<dim3(QLEN / 64, H_HEADS), 128, F_SMEM>>>(Qh, Kh, Vh, Oh);

    gemm_o<<<dim3(HIDDEN / 64, QLEN / 128), 256, GO_SMEM>>>(Oh, Woh, out);
}